// round 1
// baseline (speedup 1.0000x reference)
#include <cuda_runtime.h>
#include <cstdint>

// ---------------- problem dims (fixed) ----------------
#define TOKENS (8*4096)   // B*L = 32768
#define DMODEL 256
#define DINNER 384
#define DSTATE 8
#define NXZ (3*DINNER)    // 1152

// ---------------- scratch (static device, no allocs) ----------------
__device__ float g_xn[(size_t)TOKENS * DMODEL];   // layernorm output
__device__ float g_xz[(size_t)TOKENS * NXZ];      // silu(x_proj), silu(z), dt_in
__device__ float g_dt[(size_t)TOKENS * DINNER];   // softplus(dt)
__device__ float g_y [(size_t)TOKENS * DINNER];   // scan output (pre out-proj)

// ---------------- helpers ----------------
__device__ __forceinline__ uint32_t f2tf(float f) {
    uint32_t r;
    asm("cvt.rna.tf32.f32 %0, %1;" : "=r"(r) : "f"(f));
    return r;
}

__device__ __forceinline__ void mma_tf32(float* d, const uint32_t* a, const uint32_t* b) {
    asm volatile(
        "mma.sync.aligned.m16n8k8.row.col.f32.tf32.tf32.f32 "
        "{%0,%1,%2,%3}, {%4,%5,%6,%7}, {%8,%9}, {%0,%1,%2,%3};\n"
        : "+f"(d[0]), "+f"(d[1]), "+f"(d[2]), "+f"(d[3])
        : "r"(a[0]), "r"(a[1]), "r"(a[2]), "r"(a[3]),
          "r"(b[0]), "r"(b[1]));
}

// ---------------- LayerNorm: one warp per token ----------------
__global__ __launch_bounds__(256)
void ln_kernel(const float* __restrict__ x, const float* __restrict__ gamma,
               const float* __restrict__ beta, float* __restrict__ out) {
    int warp = threadIdx.x >> 5;
    int lane = threadIdx.x & 31;
    size_t tok = (size_t)blockIdx.x * 8 + warp;
    const float* xr = x + tok * DMODEL;
    int k = lane * 8;
    float4 v0 = *reinterpret_cast<const float4*>(xr + k);
    float4 v1 = *reinterpret_cast<const float4*>(xr + k + 4);
    float s = v0.x + v0.y + v0.z + v0.w + v1.x + v1.y + v1.z + v1.w;
    float q = v0.x*v0.x + v0.y*v0.y + v0.z*v0.z + v0.w*v0.w
            + v1.x*v1.x + v1.y*v1.y + v1.z*v1.z + v1.w*v1.w;
    #pragma unroll
    for (int off = 16; off; off >>= 1) {
        s += __shfl_xor_sync(0xffffffffu, s, off);
        q += __shfl_xor_sync(0xffffffffu, q, off);
    }
    float mu   = s * (1.0f / DMODEL);
    float var  = q * (1.0f / DMODEL) - mu * mu;
    float rstd = rsqrtf(var + 1e-5f);
    float* orow = out + tok * DMODEL;
    float4 r0, r1;
    r0.x = (v0.x - mu) * rstd * gamma[k+0] + beta[k+0];
    r0.y = (v0.y - mu) * rstd * gamma[k+1] + beta[k+1];
    r0.z = (v0.z - mu) * rstd * gamma[k+2] + beta[k+2];
    r0.w = (v0.w - mu) * rstd * gamma[k+3] + beta[k+3];
    r1.x = (v1.x - mu) * rstd * gamma[k+4] + beta[k+4];
    r1.y = (v1.y - mu) * rstd * gamma[k+5] + beta[k+5];
    r1.z = (v1.z - mu) * rstd * gamma[k+6] + beta[k+6];
    r1.w = (v1.w - mu) * rstd * gamma[k+7] + beta[k+7];
    *reinterpret_cast<float4*>(orow + k)     = r0;
    *reinterpret_cast<float4*>(orow + k + 4) = r1;
}

// ---------------- tf32 GEMM: C[M,N] = epi(A[M,K] @ W[N,K]^T + bias) ----------------
// BM=128 BN=64 BK=32, 256 threads, warp grid 4(M) x 2(N), warp tile 32x32.
// EPI: 0 = xz (silu on cols < 2*DINNER), 1 = softplus, 2 = +bias +residual
#define BM 128
#define BN 64
#define BK 32
#define BKP (BK + 4)   // pad 4 floats -> fragment loads conflict-free

template<int EPI>
__global__ __launch_bounds__(256)
void gemm_tf32(const float* __restrict__ A, int lda, int aoff,
               const float* __restrict__ W, int K,
               const float* __restrict__ bias,
               float* __restrict__ C, int ldc,
               const float* __restrict__ resid) {
    __shared__ float As[BM][BKP];
    __shared__ float Bs[BN][BKP];

    int tid = threadIdx.x;
    int wid = tid >> 5, lane = tid & 31;
    int warp_m = wid & 3;        // 0..3
    int warp_n = wid >> 2;       // 0..1
    int bm = blockIdx.y * BM;
    int bn = blockIdx.x * BN;

    float acc[2][4][4] = {};

    for (int kt = 0; kt < K; kt += BK) {
        // stage A tile (convert to tf32 at store)
        #pragma unroll
        for (int i = 0; i < 4; i++) {
            int idx = tid + i * 256;
            int row = idx >> 3;
            int jv  = (idx & 7) * 4;
            float4 v = *reinterpret_cast<const float4*>(
                &A[(size_t)(bm + row) * lda + aoff + kt + jv]);
            uint4 t;
            t.x = f2tf(v.x); t.y = f2tf(v.y); t.z = f2tf(v.z); t.w = f2tf(v.w);
            *reinterpret_cast<uint4*>(&As[row][jv]) = t;
        }
        // stage W tile
        #pragma unroll
        for (int i = 0; i < 2; i++) {
            int idx = tid + i * 256;
            int row = idx >> 3;
            int jv  = (idx & 7) * 4;
            float4 v = *reinterpret_cast<const float4*>(
                &W[(size_t)(bn + row) * K + kt + jv]);
            uint4 t;
            t.x = f2tf(v.x); t.y = f2tf(v.y); t.z = f2tf(v.z); t.w = f2tf(v.w);
            *reinterpret_cast<uint4*>(&Bs[row][jv]) = t;
        }
        __syncthreads();

        int r0 = lane >> 2, c0 = lane & 3;
        #pragma unroll
        for (int k8 = 0; k8 < BK / 8; k8++) {
            uint32_t af[2][4], bf[4][2];
            #pragma unroll
            for (int mi = 0; mi < 2; mi++) {
                int rb = warp_m * 32 + mi * 16;
                int kc = k8 * 8 + c0;
                af[mi][0] = __float_as_uint(As[rb + r0    ][kc    ]);
                af[mi][1] = __float_as_uint(As[rb + r0 + 8][kc    ]);
                af[mi][2] = __float_as_uint(As[rb + r0    ][kc + 4]);
                af[mi][3] = __float_as_uint(As[rb + r0 + 8][kc + 4]);
            }
            #pragma unroll
            for (int ni = 0; ni < 4; ni++) {
                int nb = warp_n * 32 + ni * 8;
                int kc = k8 * 8 + c0;
                bf[ni][0] = __float_as_uint(Bs[nb + r0][kc    ]);
                bf[ni][1] = __float_as_uint(Bs[nb + r0][kc + 4]);
            }
            #pragma unroll
            for (int mi = 0; mi < 2; mi++)
                #pragma unroll
                for (int ni = 0; ni < 4; ni++)
                    mma_tf32(acc[mi][ni], af[mi], bf[ni]);
        }
        __syncthreads();
    }

    // epilogue
    int r0 = lane >> 2, c0 = lane & 3;
    #pragma unroll
    for (int mi = 0; mi < 2; mi++) {
        #pragma unroll
        for (int ni = 0; ni < 4; ni++) {
            int gr = bm + warp_m * 32 + mi * 16 + r0;
            int gc = bn + warp_n * 32 + ni * 8 + c0 * 2;
            #pragma unroll
            for (int rg = 0; rg < 4; rg++) {
                int row = gr + (rg >> 1) * 8;
                int col = gc + (rg & 1);
                float v = acc[mi][ni][rg] + bias[col];
                if (EPI == 0) {
                    if (col < 2 * DINNER) v = v / (1.0f + __expf(-v));   // silu
                } else if (EPI == 1) {
                    v = fmaxf(v, 0.0f) + log1pf(__expf(-fabsf(v)));      // softplus
                } else {
                    v += resid[(size_t)row * ldc + col];
                }
                C[(size_t)row * ldc + col] = v;
            }
        }
    }
}

// ---------------- chunked scan + gating ----------------
// one thread per (b, chunk, di); h resets to 0 per 32-token chunk (faithful to ref)
__global__ __launch_bounds__(128)
void scan_kernel(const float* __restrict__ xz, const float* __restrict__ dtb,
                 const float* __restrict__ A_log, const float* __restrict__ Dvec,
                 float* __restrict__ y) {
    int di = blockIdx.x * 128 + threadIdx.x;           // 0..383
    size_t tok0 = (size_t)blockIdx.y * 32;             // bc*32 == b*4096 + c*32
    float nA[DSTATE];
    #pragma unroll
    for (int s = 0; s < DSTATE; s++)
        nA[s] = -__expf(A_log[di * DSTATE + s]);
    float Dv = Dvec[di];
    float h[DSTATE] = {};
    #pragma unroll 4
    for (int t = 0; t < 32; t++) {
        size_t tok = tok0 + t;
        float xp  = xz[tok * NXZ + di];
        float zv  = xz[tok * NXZ + DINNER + di];
        float dtv = dtb[tok * DINNER + di];
        float ys = 0.0f;
        #pragma unroll
        for (int s = 0; s < DSTATE; s++) {
            h[s] = fmaf(h[s], __expf(dtv * nA[s]), xp);
            ys += h[s];
        }
        y[tok * DINNER + di] = fmaf(ys, zv, xp * Dv);
    }
}

// ---------------- launch ----------------
extern "C" void kernel_launch(void* const* d_in, const int* in_sizes, int n_in,
                              void* d_out, int out_size) {
    (void)in_sizes; (void)n_in; (void)out_size;
    const float* x     = (const float*)d_in[0];
    const float* gamma = (const float*)d_in[1];
    const float* beta  = (const float*)d_in[2];
    const float* W_in  = (const float*)d_in[3];
    const float* b_in  = (const float*)d_in[4];
    const float* W_dt  = (const float*)d_in[5];
    const float* b_dt  = (const float*)d_in[6];
    const float* A_log = (const float*)d_in[7];
    const float* D_vec = (const float*)d_in[8];
    const float* W_out = (const float*)d_in[9];
    const float* b_out = (const float*)d_in[10];
    float* out = (float*)d_out;

    float *xn, *xz, *dt, *y;
    cudaGetSymbolAddress((void**)&xn, g_xn);
    cudaGetSymbolAddress((void**)&xz, g_xz);
    cudaGetSymbolAddress((void**)&dt, g_dt);
    cudaGetSymbolAddress((void**)&y,  g_y);

    // 1) layernorm
    ln_kernel<<<TOKENS / 8, 256>>>(x, gamma, beta, xn);

    // 2) xz = xn @ W_in^T + b_in, silu on x_proj and z parts
    gemm_tf32<0><<<dim3(NXZ / BN, TOKENS / BM), 256>>>(
        xn, DMODEL, 0, W_in, DMODEL, b_in, xz, NXZ, nullptr);

    // 3) dt = softplus(dt_in @ W_dt^T + b_dt); dt_in = xz cols [768,1152)
    gemm_tf32<1><<<dim3(DINNER / BN, TOKENS / BM), 256>>>(
        xz, NXZ, 2 * DINNER, W_dt, DINNER, b_dt, dt, DINNER, nullptr);

    // 4) chunked SSM scan + gating (y = scan*z + x_proj*D)
    scan_kernel<<<dim3(DINNER / 128, TOKENS / 32), 128>>>(
        xz, dt, A_log, D_vec, y);

    // 5) out = y @ W_out^T + b_out + residual
    gemm_tf32<2><<<dim3(DMODEL / BN, TOKENS / BM), 256>>>(
        y, DINNER, 0, W_out, DINNER, b_out, out, DMODEL, x);
}